// round 3
// baseline (speedup 1.0000x reference)
#include <cuda_runtime.h>

typedef unsigned long long u64;

#define B_    8
#define DIM_  1024
#define T_    4096
#define CB_   4096
#define CD_   8
#define BT_   (B_*T_)
#define NSL_  8
#define SLICE_ (CB_/NSL_)   // 512

static const size_t IDX_OFF_  = (size_t)B_ * DIM_ * T_;          // 33554432
static const size_t LOSS_OFF_ = (size_t)B_ * DIM_ * T_ + BT_;    // 33587200

// ---------------- device scratch (no allocations allowed) ----------------
__device__ float g_cn[CB_ * CD_];          // normalized codebook [j][c]
__device__ float g_Win[DIM_ * CD_];        // weight-normed in_proj, transposed [d][o]
__device__ float g_Wout2[DIM_ * 2 * CD_];  // weight-normed out_proj, splatted [o][c][2]
__device__ float g_bout2[DIM_ * 2];        // b_out splatted [o][2]

// ---------------- f32x2 helpers (FFMA2 only reachable via PTX) ----------------
__device__ __forceinline__ u64 f2mul(u64 a, u64 b) {
    u64 r; asm("mul.rn.f32x2 %0, %1, %2;" : "=l"(r) : "l"(a), "l"(b)); return r;
}
__device__ __forceinline__ u64 f2fma(u64 a, u64 b, u64 c) {
    u64 r; asm("fma.rn.f32x2 %0, %1, %2, %3;" : "=l"(r) : "l"(a), "l"(b), "l"(c)); return r;
}
__device__ __forceinline__ float2 f2unpack(u64 a) {
    float x, y; asm("mov.b64 {%0, %1}, %2;" : "=f"(x), "=f"(y) : "l"(a));
    return make_float2(x, y);
}
__device__ __forceinline__ u64 f2pack(float x, float y) {
    u64 r; asm("mov.b64 %0, {%1, %2};" : "=l"(r) : "f"(x), "f"(y)); return r;
}

// ---------------- prep: weight-norm scales, normalized codebook, splats ----------------
__global__ void __launch_bounds__(256) prep_kernel(
    const float* __restrict__ v_in, const float* __restrict__ g_in,
    const float* __restrict__ codebook,
    const float* __restrict__ v_out, const float* __restrict__ g_out,
    const float* __restrict__ b_out, float* __restrict__ dout)
{
    const int r = blockIdx.x * 256 + threadIdx.x;
    if (r < CB_) {
        float v[CD_]; float s = 0.f;
#pragma unroll
        for (int c = 0; c < CD_; ++c) { v[c] = codebook[(size_t)r * CD_ + c]; s += v[c] * v[c]; }
        float n = fmaxf(sqrtf(s), 1e-12f);
#pragma unroll
        for (int c = 0; c < CD_; ++c) g_cn[(size_t)r * CD_ + c] = v[c] / n;
    } else if (r < CB_ + DIM_) {
        const int o = r - CB_;
        float v[CD_]; float s = 0.f;
#pragma unroll
        for (int c = 0; c < CD_; ++c) { v[c] = v_out[(size_t)o * CD_ + c]; s += v[c] * v[c]; }
        float sc = g_out[o] / sqrtf(s);
#pragma unroll
        for (int c = 0; c < CD_; ++c) {
            float w = v[c] * sc;
            g_Wout2[o * 16 + 2 * c]     = w;
            g_Wout2[o * 16 + 2 * c + 1] = w;
        }
        float bb = b_out[o];
        g_bout2[o * 2] = bb; g_bout2[o * 2 + 1] = bb;
    } else if (r < CB_ + DIM_ + CD_ * 32) {
        const int idx  = r - (CB_ + DIM_);
        const int w    = idx >> 5;
        const int lane = idx & 31;
        float s = 0.f;
        for (int d = lane; d < DIM_; d += 32) {
            float v = v_in[(size_t)w * DIM_ + d]; s += v * v;
        }
#pragma unroll
        for (int off = 16; off > 0; off >>= 1) s += __shfl_xor_sync(0xffffffffu, s, off);
        float sc = g_in[w] / sqrtf(s);
        for (int d = lane; d < DIM_; d += 32)
            g_Win[d * CD_ + w] = v_in[(size_t)w * DIM_ + d] * sc;
    } else if (r < CB_ + DIM_ + CD_ * 32 + B_) {
        dout[LOSS_OFF_ + (r - (CB_ + DIM_ + CD_ * 32))] = 0.f;
    }
}

// ---------------- fused: ze + search + loss/idx + outproj (block = 32 timesteps) ----------------
__global__ void __launch_bounds__(256) fused_kernel(const float* __restrict__ z,
                                                    const float* __restrict__ b_in,
                                                    const float* __restrict__ codebook,
                                                    float* __restrict__ dout)
{
    __shared__ float s_part[NSL_][32][9];   // per-warp partial z_e, padded
    __shared__ float s_ze[32][CD_];         // final z_e for 32 timesteps
    __shared__ float s_q2[16][CD_][2];      // gathered codes, pair-interleaved
    __shared__ float s_bv[NSL_][32];
    __shared__ int   s_bi[NSL_][32];
    __shared__ int   s_idx[32];
    __shared__ float s_red[256];

    const int tid  = threadIdx.x;
    const int w    = tid >> 5;              // warp 0..7
    const int lane = tid & 31;
    const int tb   = blockIdx.x * 32;       // block's first timestep (never crosses batch)
    const int b    = tb >> 12;
    const int tl   = tb & (T_ - 1);

    // ---- phase 1: z_e partials. warp w reduces dim-chunk [w*128, w*128+128) for all 32 t ----
    {
        const float* zp = z + ((size_t)b * DIM_ + w * 128) * T_ + tl + lane;
        const float* wp = g_Win + (w * 128) * CD_;
        float a0 = 0.f, a1 = 0.f, a2 = 0.f, a3 = 0.f, a4 = 0.f, a5 = 0.f, a6 = 0.f, a7 = 0.f;
#pragma unroll 8
        for (int d = 0; d < 128; ++d) {
            float zv = __ldg(zp + (size_t)d * T_);          // coalesced 128B/warp
            float4 w0 = *(const float4*)(wp + d * CD_);     // warp-uniform, L1
            float4 w1 = *(const float4*)(wp + d * CD_ + 4);
            a0 = fmaf(w0.x, zv, a0); a1 = fmaf(w0.y, zv, a1);
            a2 = fmaf(w0.z, zv, a2); a3 = fmaf(w0.w, zv, a3);
            a4 = fmaf(w1.x, zv, a4); a5 = fmaf(w1.y, zv, a5);
            a6 = fmaf(w1.z, zv, a6); a7 = fmaf(w1.w, zv, a7);
        }
        float* p = s_part[w][lane];
        p[0] = a0; p[1] = a1; p[2] = a2; p[3] = a3;
        p[4] = a4; p[5] = a5; p[6] = a6; p[7] = a7;
    }
    __syncthreads();

    // cross-warp reduce: thread (t = tid>>3, c = tid&7)
    {
        const int t = tid >> 3, c = tid & 7;
        float acc = __ldg(b_in + c);
#pragma unroll
        for (int k = 0; k < NSL_; ++k) acc += s_part[k][t][c];
        s_ze[t][c] = acc;
    }
    __syncthreads();

    // ---- phase 2: search. warp w scans codebook slice w for its lane's timestep ----
    {
        const float* zr = s_ze[lane];
        u64 zA = f2pack(zr[0], zr[1]);
        u64 zB = f2pack(zr[2], zr[3]);
        u64 zC = f2pack(zr[4], zr[5]);
        u64 zD = f2pack(zr[6], zr[7]);

        float best = -3.4e38f; int bj = 0;
        const ulonglong2* cr = (const ulonglong2*)g_cn + (size_t)w * SLICE_ * 2;
#pragma unroll 4
        for (int j = 0; j < SLICE_; ++j) {
            ulonglong2 c0 = cr[2 * j], c1 = cr[2 * j + 1];  // warp-uniform -> L1 broadcast
            u64 d = f2mul(zA, c0.x);
            d = f2fma(zB, c0.y, d);
            d = f2fma(zC, c1.x, d);
            d = f2fma(zD, c1.y, d);
            float2 f = f2unpack(d);
            float dot = f.x + f.y;
            if (dot > best) { best = dot; bj = j; }          // strict > : lowest j on tie
        }
        s_bv[w][lane] = best;
        s_bi[w][lane] = bj + w * SLICE_;
    }
    __syncthreads();

    if (tid < 32) {
        float bv = s_bv[0][lane]; int bi = s_bi[0][lane];
#pragma unroll
        for (int s = 1; s < NSL_; ++s) {
            float ov = s_bv[s][lane];
            if (ov > bv) { bv = ov; bi = s_bi[s][lane]; }    // ascending s keeps lowest j
        }
        s_idx[lane] = bi;
        dout[IDX_OFF_ + tb + lane] = (float)bi;              // exactly representable
    }
    __syncthreads();

    // ---- phase 3: gather codes + loss ----
    {
        const int t = tid >> 3, c = tid & 7;
        const int idx = s_idx[t];
        float qv = __ldg(codebook + (size_t)idx * CD_ + c);
        s_q2[t >> 1][c][t & 1] = qv;
        float d_ = s_ze[t][c] - qv;
        s_red[tid] = d_ * d_;
    }
    __syncthreads();
#pragma unroll
    for (int s = 128; s > 0; s >>= 1) {
        if (tid < s) s_red[tid] += s_red[tid + s];
        __syncthreads();
    }
    if (tid == 0)
        atomicAdd(&dout[LOSS_OFF_ + b], s_red[0] * (1.25f / 32768.f));
    __syncthreads();

    // ---- phase 4: out-proj. thread = (pair p, 64-row dim chunk oc) ----
    {
        const int p  = tid & 15;            // timestep pair 0..15
        const int oc = tid >> 4;            // dim chunk 0..15
        const u64* q = (const u64*)s_q2[p];
        u64 q0 = q[0], q1 = q[1], q2 = q[2], q3 = q[3];
        u64 q4 = q[4], q5 = q[5], q6 = q[6], q7 = q[7];

        float* outp = dout + ((size_t)b * DIM_ + oc * 64) * T_ + tl + 2 * p;
        const float* wbase = g_Wout2 + oc * 64 * 16;
        const float* bbase = g_bout2 + oc * 64 * 2;

#pragma unroll 4
        for (int o = 0; o < 64; ++o) {
            const ulonglong2* wr = (const ulonglong2*)(wbase + o * 16);
            ulonglong2 w0 = wr[0], w1 = wr[1], w2 = wr[2], w3 = wr[3];
            u64 acc = *(const u64*)(bbase + o * 2);
            acc = f2fma(w0.x, q0, acc);
            acc = f2fma(w0.y, q1, acc);
            acc = f2fma(w1.x, q2, acc);
            acc = f2fma(w1.y, q3, acc);
            acc = f2fma(w2.x, q4, acc);
            acc = f2fma(w2.y, q5, acc);
            acc = f2fma(w3.x, q6, acc);
            acc = f2fma(w3.y, q7, acc);
            *(u64*)(outp + (size_t)o * T_) = acc;   // float2 store, 128B/warp contiguous
        }
    }
}

// ---------------- launcher ----------------
extern "C" void kernel_launch(void* const* d_in, const int* in_sizes, int n_in,
                              void* d_out, int out_size)
{
    const float* z        = (const float*)d_in[0];
    const float* v_in     = (const float*)d_in[1];
    const float* g_in     = (const float*)d_in[2];
    const float* b_in     = (const float*)d_in[3];
    const float* codebook = (const float*)d_in[4];
    const float* v_out    = (const float*)d_in[5];
    const float* g_out    = (const float*)d_in[6];
    const float* b_out    = (const float*)d_in[7];
    float* out = (float*)d_out;

    prep_kernel<<<22, 256>>>(v_in, g_in, codebook, v_out, g_out, b_out, out);
    fused_kernel<<<BT_ / 32, 256>>>(z, b_in, codebook, out);
}

// round 4
// speedup vs baseline: 1.1361x; 1.1361x over previous
#include <cuda_runtime.h>

typedef unsigned long long u64;

#define B_    8
#define DIM_  1024
#define T_    4096
#define CB_   4096
#define CD_   8
#define BT_   (B_*T_)
#define NSL_  8
#define SLICE_ (CB_/NSL_)   // 512

static const size_t IDX_OFF_  = (size_t)B_ * DIM_ * T_;          // 33554432
static const size_t LOSS_OFF_ = (size_t)B_ * DIM_ * T_ + BT_;    // 33587200

// ---------------- device scratch (no allocations allowed) ----------------
__device__ float g_cn2[CB_ * CD_ * 2];     // normalized codebook, splatted [j][c][2] (256 KB)
__device__ float g_Win[DIM_ * CD_];        // weight-normed in_proj, transposed [d][o]
__device__ float g_Wout2[DIM_ * 2 * CD_];  // weight-normed out_proj, splatted [o][c][2]
__device__ float g_bout2[DIM_ * 2];        // b_out splatted [o][2]
__device__ float g_ze[(size_t)BT_ * CD_];  // encodings z_e [t][c]  (1 MB)
__device__ int   g_idx[BT_];               // argmax indices
__device__ float g_qp[(size_t)BT_ * CD_];  // gathered codes, pair-interleaved [tp][c][2]

// ---------------- f32x2 helpers ----------------
__device__ __forceinline__ u64 f2mul(u64 a, u64 b) {
    u64 r; asm("mul.rn.f32x2 %0, %1, %2;" : "=l"(r) : "l"(a), "l"(b)); return r;
}
__device__ __forceinline__ u64 f2fma(u64 a, u64 b, u64 c) {
    u64 r; asm("fma.rn.f32x2 %0, %1, %2, %3;" : "=l"(r) : "l"(a), "l"(b), "l"(c)); return r;
}
__device__ __forceinline__ u64 f2add(u64 a, u64 b) {
    u64 r; asm("add.rn.f32x2 %0, %1, %2;" : "=l"(r) : "l"(a), "l"(b)); return r;
}
__device__ __forceinline__ float2 f2unpack(u64 a) {
    float x, y; asm("mov.b64 {%0, %1}, %2;" : "=f"(x), "=f"(y) : "l"(a));
    return make_float2(x, y);
}
__device__ __forceinline__ u64 f2pack(float x, float y) {
    u64 r; asm("mov.b64 %0, {%1, %2};" : "=l"(r) : "f"(x), "f"(y)); return r;
}

// ---------------- prep ----------------
__global__ void __launch_bounds__(256) prep_kernel(
    const float* __restrict__ v_in, const float* __restrict__ g_in,
    const float* __restrict__ codebook,
    const float* __restrict__ v_out, const float* __restrict__ g_out,
    const float* __restrict__ b_out, float* __restrict__ dout)
{
    const int r = blockIdx.x * 256 + threadIdx.x;
    if (r < CB_) {
        float v[CD_]; float s = 0.f;
#pragma unroll
        for (int c = 0; c < CD_; ++c) { v[c] = codebook[(size_t)r * CD_ + c]; s += v[c] * v[c]; }
        float n = fmaxf(sqrtf(s), 1e-12f);
#pragma unroll
        for (int c = 0; c < CD_; ++c) {
            float cn = v[c] / n;
            g_cn2[(size_t)r * 16 + 2 * c]     = cn;   // splat both halves
            g_cn2[(size_t)r * 16 + 2 * c + 1] = cn;
        }
    } else if (r < CB_ + DIM_) {
        const int o = r - CB_;
        float v[CD_]; float s = 0.f;
#pragma unroll
        for (int c = 0; c < CD_; ++c) { v[c] = v_out[(size_t)o * CD_ + c]; s += v[c] * v[c]; }
        float sc = g_out[o] / sqrtf(s);
#pragma unroll
        for (int c = 0; c < CD_; ++c) {
            float w = v[c] * sc;
            g_Wout2[o * 16 + 2 * c]     = w;
            g_Wout2[o * 16 + 2 * c + 1] = w;
        }
        float bb = b_out[o];
        g_bout2[o * 2] = bb; g_bout2[o * 2 + 1] = bb;
    } else if (r < CB_ + DIM_ + CD_ * 32) {
        const int idx  = r - (CB_ + DIM_);
        const int w    = idx >> 5;
        const int lane = idx & 31;
        float s = 0.f;
        for (int d = lane; d < DIM_; d += 32) {
            float v = v_in[(size_t)w * DIM_ + d]; s += v * v;
        }
#pragma unroll
        for (int off = 16; off > 0; off >>= 1) s += __shfl_xor_sync(0xffffffffu, s, off);
        float sc = g_in[w] / sqrtf(s);
        for (int d = lane; d < DIM_; d += 32)
            g_Win[d * CD_ + w] = v_in[(size_t)w * DIM_ + d] * sc;
    } else if (r < CB_ + DIM_ + CD_ * 32 + B_) {
        dout[LOSS_OFF_ + (r - (CB_ + DIM_ + CD_ * 32))] = 0.f;
    }
}

// ---------------- K1: z_e = W_in @ z + b_in  (DIM split 4-way) ----------------
__global__ void __launch_bounds__(256) ze_kernel(const float* __restrict__ z,
                                                 const float* __restrict__ b_in)
{
    const int tl = threadIdx.x & 63;
    const int dc = threadIdx.x >> 6;
    const int t  = blockIdx.x * 64 + tl;
    const int b  = t >> 12;
    const int tt = t & (T_ - 1);
    const float* zp = z + (size_t)b * DIM_ * T_ + tt + (size_t)(dc * 256) * T_;
    const float* wp = g_Win + dc * 256 * CD_;

    float a0 = 0.f, a1 = 0.f, a2 = 0.f, a3 = 0.f, a4 = 0.f, a5 = 0.f, a6 = 0.f, a7 = 0.f;
#pragma unroll 8
    for (int d = 0; d < 256; ++d) {
        float zv = __ldg(zp + (size_t)d * T_);
        float4 w0 = *(const float4*)(wp + d * CD_);
        float4 w1 = *(const float4*)(wp + d * CD_ + 4);
        a0 = fmaf(w0.x, zv, a0); a1 = fmaf(w0.y, zv, a1);
        a2 = fmaf(w0.z, zv, a2); a3 = fmaf(w0.w, zv, a3);
        a4 = fmaf(w1.x, zv, a4); a5 = fmaf(w1.y, zv, a5);
        a6 = fmaf(w1.z, zv, a6); a7 = fmaf(w1.w, zv, a7);
    }

    __shared__ float red[256 * 9];
    float* my = red + threadIdx.x * 9;
    my[0] = a0; my[1] = a1; my[2] = a2; my[3] = a3;
    my[4] = a4; my[5] = a5; my[6] = a6; my[7] = a7;
    __syncthreads();

    if (threadIdx.x < 64) {
        const int tg = blockIdx.x * 64 + threadIdx.x;
        float acc[CD_];
#pragma unroll
        for (int c = 0; c < CD_; ++c) acc[c] = __ldg(b_in + c);
#pragma unroll
        for (int k = 0; k < 4; ++k) {
            const float* p = red + (k * 64 + threadIdx.x) * 9;
#pragma unroll
            for (int c = 0; c < CD_; ++c) acc[c] += p[c];
        }
        float4* o = (float4*)(g_ze + (size_t)tg * CD_);
        o[0] = make_float4(acc[0], acc[1], acc[2], acc[3]);
        o[1] = make_float4(acc[4], acc[5], acc[6], acc[7]);
    }
}

// ---------------- K2: search. 64 t per warp (2 per lane via f32x2 halves) ----------------
__global__ void __launch_bounds__(256) search_kernel()
{
    const int w    = threadIdx.x >> 5;     // slice 0..7
    const int lane = threadIdx.x & 31;
    const int tb   = blockIdx.x * 64;

    // pack z_e: half .lo = t0 = tb+lane, half .hi = t1 = tb+32+lane
    const float4* zp0 = (const float4*)(g_ze + (size_t)(tb + lane) * CD_);
    const float4* zp1 = (const float4*)(g_ze + (size_t)(tb + 32 + lane) * CD_);
    float4 xa = zp0[0], xb = zp0[1], ya = zp1[0], yb = zp1[1];
    u64 z0 = f2pack(xa.x, ya.x), z1 = f2pack(xa.y, ya.y);
    u64 z2 = f2pack(xa.z, ya.z), z3 = f2pack(xa.w, ya.w);
    u64 z4 = f2pack(xb.x, yb.x), z5 = f2pack(xb.y, yb.y);
    u64 z6 = f2pack(xb.z, yb.z), z7 = f2pack(xb.w, yb.w);

    float best0 = -3.4e38f, best1 = -3.4e38f;
    int i0 = 0, i1 = 0;

    const ulonglong2* cr = (const ulonglong2*)(g_cn2 + (size_t)w * SLICE_ * 16);
#pragma unroll 2
    for (int j = 0; j < SLICE_; ++j) {
        ulonglong2 k0 = cr[0], k1 = cr[1], k2 = cr[2], k3 = cr[3];  // warp-uniform
        cr += 4;
        u64 dA = f2fma(z1, k0.y, f2mul(z0, k0.x));   // two 4-deep chains
        dA = f2fma(z2, k1.x, dA);
        dA = f2fma(z3, k1.y, dA);
        u64 dB = f2fma(z5, k2.y, f2mul(z4, k2.x));
        dB = f2fma(z6, k3.x, dB);
        dB = f2fma(z7, k3.y, dB);
        float2 f = f2unpack(f2add(dA, dB));          // .x = dot(t0), .y = dot(t1)
        if (f.x > best0) { best0 = f.x; i0 = j; }    // strict > : lowest j on tie
        if (f.y > best1) { best1 = f.y; i1 = j; }
    }

    __shared__ float s_bv[NSL_][64];
    __shared__ int   s_bi[NSL_][64];
    s_bv[w][lane]      = best0;  s_bi[w][lane]      = i0 + w * SLICE_;
    s_bv[w][lane + 32] = best1;  s_bi[w][lane + 32] = i1 + w * SLICE_;
    __syncthreads();

    if (threadIdx.x < 64) {
        float bv = s_bv[0][threadIdx.x]; int bi = s_bi[0][threadIdx.x];
#pragma unroll
        for (int s = 1; s < NSL_; ++s) {
            float ov = s_bv[s][threadIdx.x];
            if (ov > bv) { bv = ov; bi = s_bi[s][threadIdx.x]; }   // ascending s keeps lowest j
        }
        g_idx[tb + threadIdx.x] = bi;
    }
}

// ---------------- K3: finalize — indices out, loss, gather + interleave codes ----------------
__global__ void __launch_bounds__(256) finalize_kernel(const float* __restrict__ codebook,
                                                       float* __restrict__ dout)
{
    const int t = blockIdx.x * 256 + threadIdx.x;
    const int b = t >> 12;
    const int idx = g_idx[t];

    dout[IDX_OFF_ + t] = (float)idx;

    float4 q0 = __ldg((const float4*)(codebook + (size_t)idx * CD_));
    float4 q1 = __ldg((const float4*)(codebook + (size_t)idx * CD_) + 1);
    const float4* er = (const float4*)(g_ze + (size_t)t * CD_);
    float4 e0 = er[0], e1 = er[1];

    float l = 0.f, d_;
    d_ = e0.x - q0.x; l += d_ * d_;  d_ = e0.y - q0.y; l += d_ * d_;
    d_ = e0.z - q0.z; l += d_ * d_;  d_ = e0.w - q0.w; l += d_ * d_;
    d_ = e1.x - q1.x; l += d_ * d_;  d_ = e1.y - q1.y; l += d_ * d_;
    d_ = e1.z - q1.z; l += d_ * d_;  d_ = e1.w - q1.w; l += d_ * d_;

    float* qp = g_qp + (size_t)(t >> 1) * 16 + (t & 1);
    qp[0]  = q0.x; qp[2]  = q0.y; qp[4]  = q0.z; qp[6]  = q0.w;
    qp[8]  = q1.x; qp[10] = q1.y; qp[12] = q1.z; qp[14] = q1.w;

    __shared__ float sl[256];
    sl[threadIdx.x] = l;
    __syncthreads();
#pragma unroll
    for (int s = 128; s > 0; s >>= 1) {
        if (threadIdx.x < s) sl[threadIdx.x] += sl[threadIdx.x + s];
        __syncthreads();
    }
    if (threadIdx.x == 0)
        atomicAdd(&dout[LOSS_OFF_ + b], sl[0] * (1.25f / 32768.f));
}

// ---------------- K4: out-proj. Warp owns 4 o-rows in registers, sweeps 8x32 t-pairs ----------------
__global__ void __launch_bounds__(256) outproj_kernel(float* __restrict__ dout)
{
    const int w    = threadIdx.x >> 5;
    const int lane = threadIdx.x & 31;
    const int wg   = blockIdx.x * 8 + w;     // 0..16383
    const int quad = wg >> 6;                // o-quad 0..255
    const int gch  = wg & 63;                // pair-group chunk 0..63

    // weights for 4 output rows, resident in registers (uniform loads, once per warp)
    ulonglong2 Wa[4], Wb[4], Wc[4], Wd[4];
    u64 bias[4];
#pragma unroll
    for (int r = 0; r < 4; ++r) {
        const ulonglong2* wr = (const ulonglong2*)(g_Wout2 + (quad * 4 + r) * 16);
        Wa[r] = wr[0]; Wb[r] = wr[1];        // 8 u64 weight pairs per row
        Wc[r].x = Wa[r].x; Wc[r].y = Wa[r].y;  // (aliases kept trivial; compiler folds)
        Wd[r].x = Wb[r].x; Wd[r].y = Wb[r].y;
        bias[r] = *(const u64*)(g_bout2 + (quad * 4 + r) * 2);
    }

#pragma unroll
    for (int it = 0; it < 8; ++it) {
        const int p  = (gch * 8 + it) * 32 + lane;   // t-pair, lanes consecutive
        const int t0 = p << 1;
        const int b  = t0 >> 12;
        const int tl = t0 & (T_ - 1);

        const ulonglong2* qr = (const ulonglong2*)(g_qp + (size_t)p * 16);
        ulonglong2 qA = qr[0], qB = qr[1], qC = qr[2], qD = qr[3];   // 8 u64 code pairs

        float* outp = dout + ((size_t)b * DIM_ + quad * 4) * T_ + tl;
#pragma unroll
        for (int r = 0; r < 4; ++r) {
            const float* wrow = g_Wout2 + (quad * 4 + r) * 16;  // (register-cached above)
            u64 acc = bias[r];
            acc = f2fma(Wa[r].x, qA.x, acc);
            acc = f2fma(Wa[r].y, qA.y, acc);
            acc = f2fma(Wb[r].x, qB.x, acc);
            acc = f2fma(Wb[r].y, qB.y, acc);
            acc = f2fma(((const ulonglong2*)wrow)[2].x, qC.x, acc);
            acc = f2fma(((const ulonglong2*)wrow)[2].y, qC.y, acc);
            acc = f2fma(((const ulonglong2*)wrow)[3].x, qD.x, acc);
            acc = f2fma(((const ulonglong2*)wrow)[3].y, qD.y, acc);
            *(u64*)(outp + (size_t)r * T_) = acc;
        }
    }
}

// ---------------- launcher ----------------
extern "C" void kernel_launch(void* const* d_in, const int* in_sizes, int n_in,
                              void* d_out, int out_size)
{
    const float* z        = (const float*)d_in[0];
    const float* v_in     = (const float*)d_in[1];
    const float* g_in     = (const float*)d_in[2];
    const float* b_in     = (const float*)d_in[3];
    const float* codebook = (const float*)d_in[4];
    const float* v_out    = (const float*)d_in[5];
    const float* g_out    = (const float*)d_in[6];
    const float* b_out    = (const float*)d_in[7];
    float* out = (float*)d_out;

    prep_kernel<<<22, 256>>>(v_in, g_in, codebook, v_out, g_out, b_out, out);
    ze_kernel<<<BT_ / 64, 256>>>(z, b_in);
    search_kernel<<<BT_ / 64, 256>>>();
    finalize_kernel<<<BT_ / 256, 256>>>(codebook, out);
    outproj_kernel<<<2048, 256>>>(out);
}